// round 7
// baseline (speedup 1.0000x reference)
#include <cuda_runtime.h>
#include <math.h>
#include <stdint.h>

#define N_NODES_MAX 100000
#define N_EDGES_MAX 1600000
#define F_IN  128
#define HID   128
#define N_CLS 40
#define SCAN_B 1024

// ---------------- scratch (static device globals) ---------------------------
__device__ __align__(16) float g_dinv[N_NODES_MAX];
__device__ __align__(16) float g_h1 [(size_t)N_NODES_MAX * HID];
__device__ __align__(16) float g_p2 [(size_t)N_NODES_MAX * N_CLS];
__device__ int   g_cnt[N_NODES_MAX];
__device__ int   g_cursor[N_NODES_MAX];
__device__ int   g_rowstart[N_NODES_MAX + 1];
__device__ int   g_bsum[128];
__device__ int   g_boff[128];
__device__ int   g_csr_src[N_EDGES_MAX];
__device__ int   g_idx64;

// ---------------- helpers ----------------------------------------------------
__device__ __forceinline__ int load_idx(const void* ei, long long pos, int is64) {
    return is64 ? (int)((const long long*)ei)[pos] : ((const int*)ei)[pos];
}
__device__ __forceinline__ unsigned to_tf32(float x) {
    float y;
    asm("cvt.rna.tf32.f32 %0, %1;" : "=f"(y) : "f"(x));
    return __float_as_uint(y);
}

// ---------------- CSR build (fused chain) ------------------------------------
__global__ void zero_detect(int n) {
    int i = blockIdx.x * blockDim.x + threadIdx.x;
    if (i < n) g_cnt[i] = 0;
    if (i == 0) g_idx64 = 1;
}
__global__ void detect_scan(const int* __restrict__ ei32, int E) {
    int i = blockIdx.x * blockDim.x + threadIdx.x;
    long long stride = (2LL * E) / 1024;
    if (stride < 2) stride = 2;
    long long pos = ((long long)i * stride) | 1LL;
    if (pos < 2LL * E && ei32[pos] != 0) g_idx64 = 0;
}
__global__ void deg_count(const void* __restrict__ ei, int E, int N) {
    int e = blockIdx.x * blockDim.x + threadIdx.x;
    if (e >= E) return;
    int is64 = g_idx64;
    int d = load_idx(ei, (long long)E + e, is64);
    if ((unsigned)d < (unsigned)N) atomicAdd(&g_cnt[d], 1);
}
__global__ void scan1(int n) {            // block scan + dinv fused
    __shared__ int sh[SCAN_B];
    int t = threadIdx.x, b = blockIdx.x;
    int i = b * SCAN_B + t;
    int v = (i < n) ? g_cnt[i] : 0;
    if (i < n) g_dinv[i] = rsqrtf(1.0f + (float)v);
    sh[t] = v;
    __syncthreads();
    for (int o = 1; o < SCAN_B; o <<= 1) {
        int x = (t >= o) ? sh[t - o] : 0;
        __syncthreads();
        sh[t] += x;
        __syncthreads();
    }
    if (i < n) g_rowstart[i] = sh[t] - v;
    if (t == SCAN_B - 1) g_bsum[b] = sh[t];
}
__global__ void scan2(int nb) {
    __shared__ int sh[SCAN_B];
    int t = threadIdx.x;
    int v = (t < nb) ? g_bsum[t] : 0;
    sh[t] = v;
    __syncthreads();
    for (int o = 1; o < SCAN_B; o <<= 1) {
        int x = (t >= o) ? sh[t - o] : 0;
        __syncthreads();
        sh[t] += x;
        __syncthreads();
    }
    if (t < nb) g_boff[t] = sh[t] - v;
}
__global__ void scan3(int n, int E) {     // finalize rowstart, seed cursors
    int i = blockIdx.x * blockDim.x + threadIdx.x;
    if (i < n) {
        int v = g_rowstart[i] + g_boff[i / SCAN_B];
        g_rowstart[i] = v;
        g_cursor[i]   = v;
    }
    if (i == 0) g_rowstart[n] = E;
}
__global__ void csr_fill(const void* __restrict__ ei, int E, int N) {
    int e = blockIdx.x * blockDim.x + threadIdx.x;
    if (e >= E) return;
    int is64 = g_idx64;
    int s = load_idx(ei, e, is64);
    int d = load_idx(ei, (long long)E + e, is64);
    if ((unsigned)s >= (unsigned)N || (unsigned)d >= (unsigned)N) return;
    g_csr_src[atomicAdd(&g_cursor[d], 1)] = s;
}

// ---------------- GEMM1: g_h1 = x @ W1 via tf32 mma.sync --------------------
#define AS_STRIDE 132
#define BS_STRIDE 136
#define GEMM1_SMEM ((128 * AS_STRIDE + 128 * BS_STRIDE) * 4)

__global__ __launch_bounds__(256) void gemm1_tf32(const float* __restrict__ A,
                                                  const float* __restrict__ B, int M) {
    extern __shared__ float sm[];
    float* As = sm;
    float* Bs = sm + 128 * AS_STRIDE;
    int tid = threadIdx.x;
    int row0 = blockIdx.x * 128;

    #pragma unroll
    for (int i = 0; i < 16; i++) {
        int lin = tid + 256 * i;
        int r = lin >> 5, kq = lin & 31;
        float4 v = make_float4(0.f, 0.f, 0.f, 0.f);
        if (row0 + r < M) v = *(const float4*)(A + (size_t)(row0 + r) * 128 + kq * 4);
        float* p = As + r * AS_STRIDE + kq * 4;
        p[0] = __uint_as_float(to_tf32(v.x));
        p[1] = __uint_as_float(to_tf32(v.y));
        p[2] = __uint_as_float(to_tf32(v.z));
        p[3] = __uint_as_float(to_tf32(v.w));
    }
    #pragma unroll
    for (int i = 0; i < 16; i++) {
        int lin = tid + 256 * i;
        int k = lin >> 5, nq = lin & 31;
        float4 v = *(const float4*)(B + (size_t)k * 128 + nq * 4);
        float* p = Bs + k * BS_STRIDE + nq * 4;
        p[0] = __uint_as_float(to_tf32(v.x));
        p[1] = __uint_as_float(to_tf32(v.y));
        p[2] = __uint_as_float(to_tf32(v.z));
        p[3] = __uint_as_float(to_tf32(v.w));
    }
    __syncthreads();

    int warp = tid >> 5, lane = tid & 31;
    int wm = (warp & 3) * 32;
    int wn = (warp >> 2) * 64;
    int gid = lane >> 2, tig = lane & 3;

    float acc[2][8][4] = {};

    #pragma unroll
    for (int ks = 0; ks < 16; ks++) {
        int k = ks * 8;
        unsigned af[2][4];
        #pragma unroll
        for (int mt = 0; mt < 2; mt++) {
            const float* base = As + (size_t)(wm + mt * 16 + gid) * AS_STRIDE + k + tig;
            af[mt][0] = __float_as_uint(base[0]);
            af[mt][1] = __float_as_uint(base[8 * AS_STRIDE]);
            af[mt][2] = __float_as_uint(base[4]);
            af[mt][3] = __float_as_uint(base[8 * AS_STRIDE + 4]);
        }
        #pragma unroll
        for (int nt = 0; nt < 8; nt++) {
            int n = wn + nt * 8 + gid;
            unsigned b0 = __float_as_uint(Bs[(size_t)(k + tig) * BS_STRIDE + n]);
            unsigned b1 = __float_as_uint(Bs[(size_t)(k + tig + 4) * BS_STRIDE + n]);
            #pragma unroll
            for (int mt = 0; mt < 2; mt++) {
                asm volatile(
                    "mma.sync.aligned.m16n8k8.row.col.f32.tf32.tf32.f32 "
                    "{%0,%1,%2,%3}, {%4,%5,%6,%7}, {%8,%9}, {%0,%1,%2,%3};\n"
                    : "+f"(acc[mt][nt][0]), "+f"(acc[mt][nt][1]),
                      "+f"(acc[mt][nt][2]), "+f"(acc[mt][nt][3])
                    : "r"(af[mt][0]), "r"(af[mt][1]), "r"(af[mt][2]), "r"(af[mt][3]),
                      "r"(b0), "r"(b1));
            }
        }
    }

    #pragma unroll
    for (int mt = 0; mt < 2; mt++) {
        int r = row0 + wm + mt * 16 + gid;
        #pragma unroll
        for (int nt = 0; nt < 8; nt++) {
            int c = wn + nt * 8 + tig * 2;
            if (r < M)
                *(float2*)(g_h1 + (size_t)r * 128 + c) =
                    make_float2(acc[mt][nt][0], acc[mt][nt][1]);
            if (r + 8 < M)
                *(float2*)(g_h1 + (size_t)(r + 8) * 128 + c) =
                    make_float2(acc[mt][nt][2], acc[mt][nt][3]);
        }
    }
}

// ---------------- fused agg1 + relu + GEMM2: p2 = relu(Â h1 + b1) @ W2 ------
// Persistent grid-stride kernel, 8 node-warps per 256-thread block.
// W2 (128x40) + b1 staged in smem once per block; aggregation result never
// leaves the SM (epilogue projects 128 -> 40 through smem).
#define AGG_BLOCKS 1184
__global__ __launch_bounds__(256) void agg_gemm2(const float* __restrict__ b1,
                                                 const float* __restrict__ W2, int N) {
    __shared__ float W2s[128 * N_CLS];   // [f][c], c contiguous
    __shared__ float b1s[128];
    __shared__ float hbuf[8][128];       // per-warp relu'd aggregate

    int tid = threadIdx.x;
    int warp = tid >> 5, lane = tid & 31;

    for (int i = tid; i < 128 * N_CLS; i += 256) W2s[i] = W2[i];
    if (tid < 128) b1s[tid] = b1[tid];
    __syncthreads();

    for (int node = blockIdx.x * 8 + warp; node < N; node += AGG_BLOCKS * 8) {
        float di = g_dinv[node];
        float4 acc = ((const float4*)(g_h1 + (size_t)node * HID))[lane];
        float sq = di * di;
        acc.x *= sq; acc.y *= sq; acc.z *= sq; acc.w *= sq;

        int js = g_rowstart[node], je = g_rowstart[node + 1];
        for (int j0 = js; j0 < je; j0 += 32) {
            int rem = je - j0;
            int src = 0; float nrm = 0.0f;
            if (lane < rem) {
                src = g_csr_src[j0 + lane];
                nrm = g_dinv[src] * di;
            }
            int cnt = rem < 32 ? rem : 32;
            int k = 0;
            for (; k + 4 <= cnt; k += 4) {
                int s0 = __shfl_sync(0xFFFFFFFFu, src, k + 0);
                int s1 = __shfl_sync(0xFFFFFFFFu, src, k + 1);
                int s2 = __shfl_sync(0xFFFFFFFFu, src, k + 2);
                int s3 = __shfl_sync(0xFFFFFFFFu, src, k + 3);
                float n0 = __shfl_sync(0xFFFFFFFFu, nrm, k + 0);
                float n1 = __shfl_sync(0xFFFFFFFFu, nrm, k + 1);
                float n2 = __shfl_sync(0xFFFFFFFFu, nrm, k + 2);
                float n3 = __shfl_sync(0xFFFFFFFFu, nrm, k + 3);
                float4 v0 = ((const float4*)(g_h1 + (size_t)s0 * HID))[lane];
                float4 v1 = ((const float4*)(g_h1 + (size_t)s1 * HID))[lane];
                float4 v2 = ((const float4*)(g_h1 + (size_t)s2 * HID))[lane];
                float4 v3 = ((const float4*)(g_h1 + (size_t)s3 * HID))[lane];
                acc.x += v0.x*n0 + v1.x*n1 + v2.x*n2 + v3.x*n3;
                acc.y += v0.y*n0 + v1.y*n1 + v2.y*n2 + v3.y*n3;
                acc.z += v0.z*n0 + v1.z*n1 + v2.z*n2 + v3.z*n3;
                acc.w += v0.w*n0 + v1.w*n1 + v2.w*n2 + v3.w*n3;
            }
            for (; k < cnt; k++) {
                int   s = __shfl_sync(0xFFFFFFFFu, src, k);
                float n = __shfl_sync(0xFFFFFFFFu, nrm, k);
                float4 v = ((const float4*)(g_h1 + (size_t)s * HID))[lane];
                acc.x += v.x*n; acc.y += v.y*n; acc.z += v.z*n; acc.w += v.w*n;
            }
        }

        // relu(acc + b1) -> smem, then project 128 -> 40 via W2s
        const float* bb = b1s + lane * 4;
        float4 r = make_float4(fmaxf(acc.x + bb[0], 0.0f),
                               fmaxf(acc.y + bb[1], 0.0f),
                               fmaxf(acc.z + bb[2], 0.0f),
                               fmaxf(acc.w + bb[3], 0.0f));
        *(float4*)&hbuf[warp][lane * 4] = r;
        __syncwarp();

        float o0 = 0.0f, o1 = 0.0f;
        const float* hb = hbuf[warp];
        #pragma unroll 4
        for (int f = 0; f < 128; f++) {
            float hv = hb[f];                       // smem broadcast
            o0 += hv * W2s[f * N_CLS + lane];       // conflict-free (c across lanes)
            if (lane < 8) o1 += hv * W2s[f * N_CLS + 32 + lane];
        }
        g_p2[(size_t)node * N_CLS + lane] = o0;
        if (lane < 8) g_p2[(size_t)node * N_CLS + 32 + lane] = o1;
        __syncwarp();
    }
}

// ---------------- agg2 + log_softmax fused: F=40, warp-per-node -------------
__global__ void agg_f40_lsm(const float* __restrict__ b2, float* __restrict__ out, int N) {
    int warp = (blockIdx.x * blockDim.x + threadIdx.x) >> 5;
    if (warp >= N) return;
    int lane = threadIdx.x & 31;

    float di = g_dinv[warp];
    float sq = di * di;
    const float* prow = g_p2 + (size_t)warp * N_CLS;
    float a0 = prow[lane] * sq;
    float a1 = (lane < 8) ? prow[lane + 32] * sq : 0.0f;

    int js = g_rowstart[warp], je = g_rowstart[warp + 1];
    for (int j0 = js; j0 < je; j0 += 32) {
        int rem = je - j0;
        int src = 0; float nrm = 0.0f;
        if (lane < rem) {
            src = g_csr_src[j0 + lane];
            nrm = g_dinv[src] * di;
        }
        int cnt = rem < 32 ? rem : 32;
        int k = 0;
        for (; k + 4 <= cnt; k += 4) {
            int s0 = __shfl_sync(0xFFFFFFFFu, src, k + 0);
            int s1 = __shfl_sync(0xFFFFFFFFu, src, k + 1);
            int s2 = __shfl_sync(0xFFFFFFFFu, src, k + 2);
            int s3 = __shfl_sync(0xFFFFFFFFu, src, k + 3);
            float n0 = __shfl_sync(0xFFFFFFFFu, nrm, k + 0);
            float n1 = __shfl_sync(0xFFFFFFFFu, nrm, k + 1);
            float n2 = __shfl_sync(0xFFFFFFFFu, nrm, k + 2);
            float n3 = __shfl_sync(0xFFFFFFFFu, nrm, k + 3);
            const float* r0 = g_p2 + (size_t)s0 * N_CLS;
            const float* r1 = g_p2 + (size_t)s1 * N_CLS;
            const float* r2 = g_p2 + (size_t)s2 * N_CLS;
            const float* r3 = g_p2 + (size_t)s3 * N_CLS;
            a0 += r0[lane]*n0 + r1[lane]*n1 + r2[lane]*n2 + r3[lane]*n3;
            if (lane < 8)
                a1 += r0[lane+32]*n0 + r1[lane+32]*n1 + r2[lane+32]*n2 + r3[lane+32]*n3;
        }
        for (; k < cnt; k++) {
            int   s = __shfl_sync(0xFFFFFFFFu, src, k);
            float n = __shfl_sync(0xFFFFFFFFu, nrm, k);
            const float* r = g_p2 + (size_t)s * N_CLS;
            a0 += r[lane] * n;
            if (lane < 8) a1 += r[lane + 32] * n;
        }
    }

    float z0 = a0 + b2[lane];
    float z1 = (lane < 8) ? a1 + b2[lane + 32] : -1e30f;
    float m = fmaxf(z0, z1);
    #pragma unroll
    for (int o = 16; o; o >>= 1) m = fmaxf(m, __shfl_xor_sync(0xFFFFFFFFu, m, o));
    float s = expf(z0 - m) + ((lane < 8) ? expf(z1 - m) : 0.0f);
    #pragma unroll
    for (int o = 16; o; o >>= 1) s += __shfl_xor_sync(0xFFFFFFFFu, s, o);
    float lse = m + logf(s);
    out[(size_t)warp * N_CLS + lane] = z0 - lse;
    if (lane < 8) out[(size_t)warp * N_CLS + lane + 32] = z1 - lse;
}

// ---------------- launcher ---------------------------------------------------
extern "C" void kernel_launch(void* const* d_in, const int* in_sizes, int n_in,
                              void* d_out, int out_size) {
    const float* x  = (const float*)d_in[0];
    const void*  ei = d_in[1];
    const float* W1 = (const float*)d_in[2];
    const float* b1 = (const float*)d_in[3];
    const float* W2 = (const float*)d_in[4];
    const float* b2 = (const float*)d_in[5];
    float* out = (float*)d_out;

    int N = in_sizes[0] / F_IN;
    int E = in_sizes[1] / 2;
    if (N > N_NODES_MAX) N = N_NODES_MAX;
    if (E > N_EDGES_MAX) E = N_EDGES_MAX;

    const int TB = 256;
    int nb = (N + SCAN_B - 1) / SCAN_B;

    cudaFuncSetAttribute(gemm1_tf32,
                         cudaFuncAttributeMaxDynamicSharedMemorySize, GEMM1_SMEM);

    static cudaStream_t s2 = nullptr;
    static cudaEvent_t evF = nullptr, evJ = nullptr;
    if (!s2) {
        cudaStreamCreateWithFlags(&s2, cudaStreamNonBlocking);
        cudaEventCreateWithFlags(&evF, cudaEventDisableTiming);
        cudaEventCreateWithFlags(&evJ, cudaEventDisableTiming);
    }

    // fork: CSR build on s2, GEMM1 (tensor pipe) on main stream
    cudaEventRecord(evF, 0);
    cudaStreamWaitEvent(s2, evF, 0);

    zero_detect<<<(N + TB - 1) / TB, TB, 0, s2>>>(N);
    detect_scan<<<4, 256, 0, s2>>>((const int*)ei, E);
    deg_count  <<<(E + TB - 1) / TB, TB, 0, s2>>>(ei, E, N);
    scan1<<<nb, SCAN_B, 0, s2>>>(N);
    scan2<<<1, SCAN_B, 0, s2>>>(nb);
    scan3<<<(N + TB - 1) / TB, TB, 0, s2>>>(N, E);
    csr_fill<<<(E + TB - 1) / TB, TB, 0, s2>>>(ei, E, N);
    cudaEventRecord(evJ, s2);

    gemm1_tf32<<<(N + 127) / 128, 256, GEMM1_SMEM>>>(x, W1, N);

    // join
    cudaStreamWaitEvent(0, evJ, 0);

    // fused: aggregate layer 1 + relu + project to 40 classes (no agg1 buffer)
    agg_gemm2<<<AGG_BLOCKS, 256>>>(b1, W2, N);

    // fused: aggregate layer 2 + bias + log_softmax
    agg_f40_lsm<<<(N * 32 + TB - 1) / TB, TB>>>(b2, out, N);
}

// round 8
// speedup vs baseline: 1.2075x; 1.2075x over previous
#include <cuda_runtime.h>
#include <cuda_fp16.h>
#include <math.h>
#include <stdint.h>

#define N_NODES_MAX 100000
#define N_EDGES_MAX 1600000
#define F_IN  128
#define HID   128
#define N_CLS 40
#define SCAN_B 1024

// ---------------- scratch (static device globals) ---------------------------
__device__ __align__(16) float  g_dinv[N_NODES_MAX];
__device__ __align__(16) __half g_h1h[(size_t)N_NODES_MAX * HID];   // x @ W1 (fp16)
__device__ __align__(16) float  g_agg1[(size_t)N_NODES_MAX * HID];  // Agg(h1) fp32
__device__ __align__(16) float  g_p2 [(size_t)N_NODES_MAX * N_CLS];
__device__ int   g_cnt[N_NODES_MAX];
__device__ int   g_cursor[N_NODES_MAX];
__device__ int   g_rowstart[N_NODES_MAX + 1];
__device__ int   g_bsum[128];
__device__ int   g_boff[128];
__device__ int   g_csr_src[N_EDGES_MAX];
__device__ int   g_idx64;

// ---------------- helpers ----------------------------------------------------
__device__ __forceinline__ int load_idx(const void* ei, long long pos, int is64) {
    return is64 ? (int)((const long long*)ei)[pos] : ((const int*)ei)[pos];
}
__device__ __forceinline__ unsigned to_tf32(float x) {
    float y;
    asm("cvt.rna.tf32.f32 %0, %1;" : "=f"(y) : "f"(x));
    return __float_as_uint(y);
}

// ---------------- CSR build (fused chain) ------------------------------------
__global__ void zero_detect(int n) {
    int i = blockIdx.x * blockDim.x + threadIdx.x;
    if (i < n) g_cnt[i] = 0;
    if (i == 0) g_idx64 = 1;
}
__global__ void detect_scan(const int* __restrict__ ei32, int E) {
    int i = blockIdx.x * blockDim.x + threadIdx.x;
    long long stride = (2LL * E) / 1024;
    if (stride < 2) stride = 2;
    long long pos = ((long long)i * stride) | 1LL;
    if (pos < 2LL * E && ei32[pos] != 0) g_idx64 = 0;
}
__global__ void deg_count(const void* __restrict__ ei, int E, int N) {
    int e = blockIdx.x * blockDim.x + threadIdx.x;
    if (e >= E) return;
    int is64 = g_idx64;
    int d = load_idx(ei, (long long)E + e, is64);
    if ((unsigned)d < (unsigned)N) atomicAdd(&g_cnt[d], 1);
}
__global__ void scan1(int n) {
    __shared__ int sh[SCAN_B];
    int t = threadIdx.x, b = blockIdx.x;
    int i = b * SCAN_B + t;
    int v = (i < n) ? g_cnt[i] : 0;
    if (i < n) g_dinv[i] = rsqrtf(1.0f + (float)v);
    sh[t] = v;
    __syncthreads();
    for (int o = 1; o < SCAN_B; o <<= 1) {
        int x = (t >= o) ? sh[t - o] : 0;
        __syncthreads();
        sh[t] += x;
        __syncthreads();
    }
    if (i < n) g_rowstart[i] = sh[t] - v;
    if (t == SCAN_B - 1) g_bsum[b] = sh[t];
}
__global__ void scan2(int nb) {
    __shared__ int sh[SCAN_B];
    int t = threadIdx.x;
    int v = (t < nb) ? g_bsum[t] : 0;
    sh[t] = v;
    __syncthreads();
    for (int o = 1; o < SCAN_B; o <<= 1) {
        int x = (t >= o) ? sh[t - o] : 0;
        __syncthreads();
        sh[t] += x;
        __syncthreads();
    }
    if (t < nb) g_boff[t] = sh[t] - v;
}
__global__ void scan3(int n, int E) {
    int i = blockIdx.x * blockDim.x + threadIdx.x;
    if (i < n) {
        int v = g_rowstart[i] + g_boff[i / SCAN_B];
        g_rowstart[i] = v;
        g_cursor[i]   = v;
    }
    if (i == 0) g_rowstart[n] = E;
}
__global__ void csr_fill(const void* __restrict__ ei, int E, int N) {
    int e = blockIdx.x * blockDim.x + threadIdx.x;
    if (e >= E) return;
    int is64 = g_idx64;
    int s = load_idx(ei, e, is64);
    int d = load_idx(ei, (long long)E + e, is64);
    if ((unsigned)s >= (unsigned)N || (unsigned)d >= (unsigned)N) return;
    g_csr_src[atomicAdd(&g_cursor[d], 1)] = s;
}

// ---------------- GEMM1: g_h1h = fp16(x @ W1) via tf32 mma.sync -------------
#define AS_STRIDE 132
#define BS_STRIDE 136
#define GEMM1_SMEM ((128 * AS_STRIDE + 128 * BS_STRIDE) * 4)

__global__ __launch_bounds__(256) void gemm1_tf32(const float* __restrict__ A,
                                                  const float* __restrict__ B, int M) {
    extern __shared__ float sm[];
    float* As = sm;
    float* Bs = sm + 128 * AS_STRIDE;
    int tid = threadIdx.x;
    int row0 = blockIdx.x * 128;

    #pragma unroll
    for (int i = 0; i < 16; i++) {
        int lin = tid + 256 * i;
        int r = lin >> 5, kq = lin & 31;
        float4 v = make_float4(0.f, 0.f, 0.f, 0.f);
        if (row0 + r < M) v = *(const float4*)(A + (size_t)(row0 + r) * 128 + kq * 4);
        float* p = As + r * AS_STRIDE + kq * 4;
        p[0] = __uint_as_float(to_tf32(v.x));
        p[1] = __uint_as_float(to_tf32(v.y));
        p[2] = __uint_as_float(to_tf32(v.z));
        p[3] = __uint_as_float(to_tf32(v.w));
    }
    #pragma unroll
    for (int i = 0; i < 16; i++) {
        int lin = tid + 256 * i;
        int k = lin >> 5, nq = lin & 31;
        float4 v = *(const float4*)(B + (size_t)k * 128 + nq * 4);
        float* p = Bs + k * BS_STRIDE + nq * 4;
        p[0] = __uint_as_float(to_tf32(v.x));
        p[1] = __uint_as_float(to_tf32(v.y));
        p[2] = __uint_as_float(to_tf32(v.z));
        p[3] = __uint_as_float(to_tf32(v.w));
    }
    __syncthreads();

    int warp = tid >> 5, lane = tid & 31;
    int wm = (warp & 3) * 32;
    int wn = (warp >> 2) * 64;
    int gid = lane >> 2, tig = lane & 3;

    float acc[2][8][4] = {};

    #pragma unroll
    for (int ks = 0; ks < 16; ks++) {
        int k = ks * 8;
        unsigned af[2][4];
        #pragma unroll
        for (int mt = 0; mt < 2; mt++) {
            const float* base = As + (size_t)(wm + mt * 16 + gid) * AS_STRIDE + k + tig;
            af[mt][0] = __float_as_uint(base[0]);
            af[mt][1] = __float_as_uint(base[8 * AS_STRIDE]);
            af[mt][2] = __float_as_uint(base[4]);
            af[mt][3] = __float_as_uint(base[8 * AS_STRIDE + 4]);
        }
        #pragma unroll
        for (int nt = 0; nt < 8; nt++) {
            int n = wn + nt * 8 + gid;
            unsigned b0 = __float_as_uint(Bs[(size_t)(k + tig) * BS_STRIDE + n]);
            unsigned b1 = __float_as_uint(Bs[(size_t)(k + tig + 4) * BS_STRIDE + n]);
            #pragma unroll
            for (int mt = 0; mt < 2; mt++) {
                asm volatile(
                    "mma.sync.aligned.m16n8k8.row.col.f32.tf32.tf32.f32 "
                    "{%0,%1,%2,%3}, {%4,%5,%6,%7}, {%8,%9}, {%0,%1,%2,%3};\n"
                    : "+f"(acc[mt][nt][0]), "+f"(acc[mt][nt][1]),
                      "+f"(acc[mt][nt][2]), "+f"(acc[mt][nt][3])
                    : "r"(af[mt][0]), "r"(af[mt][1]), "r"(af[mt][2]), "r"(af[mt][3]),
                      "r"(b0), "r"(b1));
            }
        }
    }

    // epilogue: fp16 convert + store (halves all downstream gather traffic)
    #pragma unroll
    for (int mt = 0; mt < 2; mt++) {
        int r = row0 + wm + mt * 16 + gid;
        #pragma unroll
        for (int nt = 0; nt < 8; nt++) {
            int c = wn + nt * 8 + tig * 2;
            if (r < M)
                *(__half2*)(g_h1h + (size_t)r * 128 + c) =
                    __floats2half2_rn(acc[mt][nt][0], acc[mt][nt][1]);
            if (r + 8 < M)
                *(__half2*)(g_h1h + (size_t)(r + 8) * 128 + c) =
                    __floats2half2_rn(acc[mt][nt][2], acc[mt][nt][3]);
        }
    }
}

// ---------------- agg1: warp-per-node CSR gather, fp16 rows, fp32 accum -----
__device__ __forceinline__ void acc_row_h(float4& acc, const __half* row, int lane, float n) {
    uint2 raw = *(const uint2*)(row + lane * 4);      // 4 halves = 8 B per lane
    float2 f01 = __half22float2(*(__half2*)&raw.x);
    float2 f23 = __half22float2(*(__half2*)&raw.y);
    acc.x += f01.x * n; acc.y += f01.y * n;
    acc.z += f23.x * n; acc.w += f23.y * n;
}

__global__ void agg_f128(int N) {
    int warp = (blockIdx.x * blockDim.x + threadIdx.x) >> 5;
    if (warp >= N) return;
    int lane = threadIdx.x & 31;

    float di = g_dinv[warp];
    float4 acc = make_float4(0.f, 0.f, 0.f, 0.f);
    acc_row_h(acc, g_h1h + (size_t)warp * HID, lane, di * di);   // self loop

    int js = g_rowstart[warp], je = g_rowstart[warp + 1];
    for (int j0 = js; j0 < je; j0 += 32) {
        int rem = je - j0;
        int src = 0; float nrm = 0.0f;
        if (lane < rem) {
            src = g_csr_src[j0 + lane];
            nrm = g_dinv[src] * di;
        }
        int cnt = rem < 32 ? rem : 32;
        int k = 0;
        for (; k + 4 <= cnt; k += 4) {
            int s0 = __shfl_sync(0xFFFFFFFFu, src, k + 0);
            int s1 = __shfl_sync(0xFFFFFFFFu, src, k + 1);
            int s2 = __shfl_sync(0xFFFFFFFFu, src, k + 2);
            int s3 = __shfl_sync(0xFFFFFFFFu, src, k + 3);
            float n0 = __shfl_sync(0xFFFFFFFFu, nrm, k + 0);
            float n1 = __shfl_sync(0xFFFFFFFFu, nrm, k + 1);
            float n2 = __shfl_sync(0xFFFFFFFFu, nrm, k + 2);
            float n3 = __shfl_sync(0xFFFFFFFFu, nrm, k + 3);
            uint2 r0 = *(const uint2*)(g_h1h + (size_t)s0 * HID + lane * 4);
            uint2 r1 = *(const uint2*)(g_h1h + (size_t)s1 * HID + lane * 4);
            uint2 r2 = *(const uint2*)(g_h1h + (size_t)s2 * HID + lane * 4);
            uint2 r3 = *(const uint2*)(g_h1h + (size_t)s3 * HID + lane * 4);
            float2 a01, a23;
            a01 = __half22float2(*(__half2*)&r0.x); a23 = __half22float2(*(__half2*)&r0.y);
            acc.x += a01.x*n0; acc.y += a01.y*n0; acc.z += a23.x*n0; acc.w += a23.y*n0;
            a01 = __half22float2(*(__half2*)&r1.x); a23 = __half22float2(*(__half2*)&r1.y);
            acc.x += a01.x*n1; acc.y += a01.y*n1; acc.z += a23.x*n1; acc.w += a23.y*n1;
            a01 = __half22float2(*(__half2*)&r2.x); a23 = __half22float2(*(__half2*)&r2.y);
            acc.x += a01.x*n2; acc.y += a01.y*n2; acc.z += a23.x*n2; acc.w += a23.y*n2;
            a01 = __half22float2(*(__half2*)&r3.x); a23 = __half22float2(*(__half2*)&r3.y);
            acc.x += a01.x*n3; acc.y += a01.y*n3; acc.z += a23.x*n3; acc.w += a23.y*n3;
        }
        for (; k < cnt; k++) {
            int   s = __shfl_sync(0xFFFFFFFFu, src, k);
            float n = __shfl_sync(0xFFFFFFFFu, nrm, k);
            acc_row_h(acc, g_h1h + (size_t)s * HID, lane, n);
        }
    }
    *(float4*)(g_agg1 + (size_t)warp * HID + lane * 4) = acc;
}

// ---------------- GEMM2: g_p2 = relu(g_agg1 + b1) @ W2 (M x 40 x 128) -------
#define BM 64
#define BN 64
#define BK 16
__global__ __launch_bounds__(256) void gemm2(const float* __restrict__ B,
                                             int M, int N, int K,
                                             const float* __restrict__ in_bias) {
    __shared__ float As[BK][BM + 1];
    __shared__ float Bs[BK][BN];

    int tid = threadIdx.x;
    int tx = tid & 15, ty = tid >> 4;
    int row0 = blockIdx.y * BM;
    int col0 = blockIdx.x * BN;
    float acc[4][4] = {};

    int ka = tid & 15, ma = tid >> 4;
    int nb = tid & 63, kb = tid >> 6;

    for (int k0 = 0; k0 < K; k0 += BK) {
        #pragma unroll
        for (int j = 0; j < 4; j++) {
            int m = ma + 16 * j, gm = row0 + m;
            float v = 0.0f;
            if (gm < M)
                v = fmaxf(g_agg1[(size_t)gm * K + k0 + ka] + in_bias[k0 + ka], 0.0f);
            As[ka][m] = v;
        }
        #pragma unroll
        for (int j = 0; j < 4; j++) {
            int k = kb + 4 * j, gn = col0 + nb;
            Bs[k][nb] = (gn < N) ? B[(size_t)(k0 + k) * N + gn] : 0.0f;
        }
        __syncthreads();
        #pragma unroll
        for (int kk = 0; kk < BK; kk++) {
            float a[4], b[4];
            #pragma unroll
            for (int i = 0; i < 4; i++) a[i] = As[kk][ty + 16 * i];
            #pragma unroll
            for (int j = 0; j < 4; j++) b[j] = Bs[kk][tx + 16 * j];
            #pragma unroll
            for (int i = 0; i < 4; i++)
                #pragma unroll
                for (int j = 0; j < 4; j++)
                    acc[i][j] += a[i] * b[j];
        }
        __syncthreads();
    }
    #pragma unroll
    for (int i = 0; i < 4; i++) {
        int r = row0 + ty + 16 * i;
        if (r >= M) continue;
        #pragma unroll
        for (int j = 0; j < 4; j++) {
            int c = col0 + tx + 16 * j;
            if (c < N) g_p2[(size_t)r * N + c] = acc[i][j];
        }
    }
}

// ---------------- agg2 + log_softmax fused: F=40, warp-per-node -------------
__global__ void agg_f40_lsm(const float* __restrict__ b2, float* __restrict__ out, int N) {
    int warp = (blockIdx.x * blockDim.x + threadIdx.x) >> 5;
    if (warp >= N) return;
    int lane = threadIdx.x & 31;

    float di = g_dinv[warp];
    float sq = di * di;
    const float* prow = g_p2 + (size_t)warp * N_CLS;
    float a0 = prow[lane] * sq;
    float a1 = (lane < 8) ? prow[lane + 32] * sq : 0.0f;

    int js = g_rowstart[warp], je = g_rowstart[warp + 1];
    for (int j0 = js; j0 < je; j0 += 32) {
        int rem = je - j0;
        int src = 0; float nrm = 0.0f;
        if (lane < rem) {
            src = g_csr_src[j0 + lane];
            nrm = g_dinv[src] * di;
        }
        int cnt = rem < 32 ? rem : 32;
        int k = 0;
        for (; k + 4 <= cnt; k += 4) {
            int s0 = __shfl_sync(0xFFFFFFFFu, src, k + 0);
            int s1 = __shfl_sync(0xFFFFFFFFu, src, k + 1);
            int s2 = __shfl_sync(0xFFFFFFFFu, src, k + 2);
            int s3 = __shfl_sync(0xFFFFFFFFu, src, k + 3);
            float n0 = __shfl_sync(0xFFFFFFFFu, nrm, k + 0);
            float n1 = __shfl_sync(0xFFFFFFFFu, nrm, k + 1);
            float n2 = __shfl_sync(0xFFFFFFFFu, nrm, k + 2);
            float n3 = __shfl_sync(0xFFFFFFFFu, nrm, k + 3);
            const float* r0 = g_p2 + (size_t)s0 * N_CLS;
            const float* r1 = g_p2 + (size_t)s1 * N_CLS;
            const float* r2 = g_p2 + (size_t)s2 * N_CLS;
            const float* r3 = g_p2 + (size_t)s3 * N_CLS;
            a0 += r0[lane]*n0 + r1[lane]*n1 + r2[lane]*n2 + r3[lane]*n3;
            if (lane < 8)
                a1 += r0[lane+32]*n0 + r1[lane+32]*n1 + r2[lane+32]*n2 + r3[lane+32]*n3;
        }
        for (; k < cnt; k++) {
            int   s = __shfl_sync(0xFFFFFFFFu, src, k);
            float n = __shfl_sync(0xFFFFFFFFu, nrm, k);
            const float* r = g_p2 + (size_t)s * N_CLS;
            a0 += r[lane] * n;
            if (lane < 8) a1 += r[lane + 32] * n;
        }
    }

    float z0 = a0 + b2[lane];
    float z1 = (lane < 8) ? a1 + b2[lane + 32] : -1e30f;
    float m = fmaxf(z0, z1);
    #pragma unroll
    for (int o = 16; o; o >>= 1) m = fmaxf(m, __shfl_xor_sync(0xFFFFFFFFu, m, o));
    float s = expf(z0 - m) + ((lane < 8) ? expf(z1 - m) : 0.0f);
    #pragma unroll
    for (int o = 16; o; o >>= 1) s += __shfl_xor_sync(0xFFFFFFFFu, s, o);
    float lse = m + logf(s);
    out[(size_t)warp * N_CLS + lane] = z0 - lse;
    if (lane < 8) out[(size_t)warp * N_CLS + lane + 32] = z1 - lse;
}

// ---------------- launcher ---------------------------------------------------
extern "C" void kernel_launch(void* const* d_in, const int* in_sizes, int n_in,
                              void* d_out, int out_size) {
    const float* x  = (const float*)d_in[0];
    const void*  ei = d_in[1];
    const float* W1 = (const float*)d_in[2];
    const float* b1 = (const float*)d_in[3];
    const float* W2 = (const float*)d_in[4];
    const float* b2 = (const float*)d_in[5];
    float* out = (float*)d_out;

    int N = in_sizes[0] / F_IN;
    int E = in_sizes[1] / 2;
    if (N > N_NODES_MAX) N = N_NODES_MAX;
    if (E > N_EDGES_MAX) E = N_EDGES_MAX;

    const int TB = 256;
    int nb = (N + SCAN_B - 1) / SCAN_B;

    cudaFuncSetAttribute(gemm1_tf32,
                         cudaFuncAttributeMaxDynamicSharedMemorySize, GEMM1_SMEM);

    static cudaStream_t s2 = nullptr;
    static cudaEvent_t evF = nullptr, evJ = nullptr;
    if (!s2) {
        cudaStreamCreateWithFlags(&s2, cudaStreamNonBlocking);
        cudaEventCreateWithFlags(&evF, cudaEventDisableTiming);
        cudaEventCreateWithFlags(&evJ, cudaEventDisableTiming);
    }

    // fork: CSR build on s2, GEMM1 (tensor pipe) on main stream
    cudaEventRecord(evF, 0);
    cudaStreamWaitEvent(s2, evF, 0);

    zero_detect<<<(N + TB - 1) / TB, TB, 0, s2>>>(N);
    detect_scan<<<4, 256, 0, s2>>>((const int*)ei, E);
    deg_count  <<<(E + TB - 1) / TB, TB, 0, s2>>>(ei, E, N);
    scan1<<<nb, SCAN_B, 0, s2>>>(N);
    scan2<<<1, SCAN_B, 0, s2>>>(nb);
    scan3<<<(N + TB - 1) / TB, TB, 0, s2>>>(N, E);
    csr_fill<<<(E + TB - 1) / TB, TB, 0, s2>>>(ei, E, N);
    cudaEventRecord(evJ, s2);

    gemm1_tf32<<<(N + 127) / 128, 256, GEMM1_SMEM>>>(x, W1, N);

    // join
    cudaStreamWaitEvent(0, evJ, 0);

    agg_f128<<<(N * 32 + TB - 1) / TB, TB>>>(N);
    {
        dim3 grid((N_CLS + BN - 1) / BN, (N + BM - 1) / BM);
        gemm2<<<grid, TB>>>(W2, N, N_CLS, HID, b1);
    }
    agg_f40_lsm<<<(N * 32 + TB - 1) / TB, TB>>>(b2, out, N);
}